// round 16
// baseline (speedup 1.0000x reference)
#include <cuda_runtime.h>
#include <math.h>
#include <stdint.h>

#define BMSZ 32
#define LSEQ 2048
#define NP   256
#define DM   128
#define DI   256
#define DS   16
#define DTR  8
#define PLEN 96
#define KH   (NP*DM)   /* 32768 */
#define EPSF 1e-5f

// k_in2 dynamic smem layout (floats): R1[35*132] | R2[35*260] | sdbc[32*40] | ssc[40]
#define R1S      132                  /* padded: A-frag banks (4g+tig) conflict-free */
#define R2S      260                  /* padded: dbc-MMA A-frag conflict-free */
#define R1_OFF   0
#define R2_OFF   (35*R1S)             /* 4620 */
#define SDBC_OFF (R2_OFF + 35*R2S)    /* 4620+9100 */
#define SSC_OFF  (SDBC_OFF+1280)
#define DSMEM_FLOATS (SSC_OFF+40)
#define DSMEM_BYTES  (DSMEM_FLOATS*4)

// -------- scratch (device globals; no allocation) --------
__device__ float g_mean[BMSZ];
__device__ float g_std[BMSZ];
__device__ float g_rstd[BMSZ];
__device__ __align__(16) float g_u[BMSZ*NP*DM];    // residual stream (4 MB)
__device__ __align__(16) float g_z[BMSZ*NP*DI];    // 8 MB
__device__ __align__(16) float g_dx[BMSZ*NP*DI*2]; // (delta, xs) interleaved, 16 MB
__device__ __align__(16) float g_bc[BMSZ*NP*32];   // per token, 8 quads (B_q,C_q,B_q+8,C_q+8)
__device__ __align__(16) float g_y[BMSZ*NP*DI];    // gated y (8 MB)
__device__ __align__(16) float g_part[256*BMSZ*PLEN];  // split-K head partials

__device__ __forceinline__ float siluf(float x) { return x / (1.f + __expf(-x)); }

__device__ __forceinline__ uint32_t f2tf(float x) {
    uint32_t u; asm("cvt.rna.tf32.f32 %0, %1;" : "=r"(u) : "f"(x)); return u;
}
__device__ __forceinline__ void mma_tf32(float& d0, float& d1, float& d2, float& d3,
                                         uint32_t a0, uint32_t a1, uint32_t a2, uint32_t a3,
                                         uint32_t b0, uint32_t b1) {
    asm volatile(
        "mma.sync.aligned.m16n8k8.row.col.f32.tf32.tf32.f32 "
        "{%0,%1,%2,%3},{%4,%5,%6,%7},{%8,%9},{%0,%1,%2,%3};"
        : "+f"(d0), "+f"(d1), "+f"(d2), "+f"(d3)
        : "r"(a0), "r"(a1), "r"(a2), "r"(a3), "r"(b0), "r"(b1));
}

// -------- K0: per-sequence mean/std over L --------
__global__ void k_stats(const float* __restrict__ x) {
    int bm = blockIdx.x, tid = threadIdx.x;
    float s = 0.f, s2 = 0.f;
    for (int i = tid; i < LSEQ; i += 256) {
        float v = x[bm*LSEQ + i];
        s += v; s2 += v*v;
    }
    __shared__ float sa[256], sb[256];
    sa[tid] = s; sb[tid] = s2; __syncthreads();
    for (int off = 128; off > 0; off >>= 1) {
        if (tid < off) { sa[tid] += sa[tid+off]; sb[tid] += sb[tid+off]; }
        __syncthreads();
    }
    if (tid == 0) {
        float m = sa[0] * (1.f/LSEQ);
        float var = sb[0] * (1.f/LSEQ) - m*m;
        float st = sqrtf(var + EPSF);
        g_mean[bm] = m; g_std[bm] = st; g_rstd[bm] = 1.f/st;
    }
}

// -------- K1: patch embedding: u = patches @ W_pe + b_pe + pos --------
__global__ void k_embed(const float* __restrict__ x, const float* __restrict__ W_pe,
                        const float* __restrict__ b_pe, const float* __restrict__ pos) {
    int p = blockIdx.x, bm = blockIdx.y, j = threadIdx.x;  // 128 threads
    __shared__ float sp[16];
    if (j < 16) {
        int t = p*8 + j; if (t > LSEQ-1) t = LSEQ-1;       // right-pad with last value
        sp[j] = (x[bm*LSEQ + t] - g_mean[bm]) * g_rstd[bm];
    }
    __syncthreads();
    float acc = b_pe[j] + pos[p*DM + j];
    #pragma unroll
    for (int k = 0; k < 16; k++) acc = fmaf(sp[k], W_pe[k*DM + j], acc);
    g_u[(bm*NP + p)*DM + j] = acc;
}

// -------- K2: RMSNorm + tf32 W_in GEMM + conv4/SiLU + tf32 dbc GEMM + delta + BC --------
__global__ void k_in2(const float* __restrict__ rms_w, const float* __restrict__ W_in,
                      const float* __restrict__ conv_w, const float* __restrict__ conv_b,
                      const float* __restrict__ W_xp, const float* __restrict__ W_dt,
                      const float* __restrict__ b_dt) {
    extern __shared__ __align__(16) float dsm[];
    float* R1   = dsm + R1_OFF;       // [35][R1S] normalized u (rows 0..2 halo)
    float* R2   = dsm + R2_OFF;       // [35][R2S] xb (then xs in rows 0..31)
    float* sdbc = dsm + SDBC_OFF;     // [32][40]
    float* ssc  = dsm + SSC_OFF;
    int row0 = blockIdx.x * 32, tid = threadIdx.x;

    bool seqstart = (row0 & (NP-1)) == 0;
    for (int i = tid; i < 32*128; i += 512) R1[(3 + (i>>7))*R1S + (i&127)] = g_u[row0*DM + i];
    if (seqstart) { for (int i = tid; i < 3*128; i += 512) R1[(i>>7)*R1S + (i&127)] = 0.f; }
    else          { for (int i = tid; i < 3*128; i += 512) R1[(i>>7)*R1S + (i&127)] = g_u[(row0-3)*DM + i]; }
    __syncthreads();

    int w = tid >> 5, lane = tid & 31;
    for (int r = w; r < 35; r += 16) {
        float ss = 0.f;
        #pragma unroll
        for (int q = 0; q < 4; q++) { float v = R1[r*R1S + lane + 32*q]; ss += v*v; }
        #pragma unroll
        for (int o = 16; o > 0; o >>= 1) ss += __shfl_xor_sync(0xffffffffu, ss, o);
        if (lane == 0) ssc[r] = rsqrtf(ss * (1.f/128.f) + EPSF);
    }
    __syncthreads();
    for (int i = tid; i < 35*128; i += 512) {
        int r = i>>7, k = i&127;
        R1[r*R1S + k] *= ssc[r] * rms_w[k];
    }
    __syncthreads();

    // halo xb rows (tokens -3..-1) scalar -> R2 rows 0..2
    if (tid < 256) {
        float h0 = 0.f, h1 = 0.f, h2 = 0.f;
        for (int k = 0; k < 128; k++) {
            float ww = __ldg(&W_in[k*512 + tid]);
            h0 = fmaf(R1[0*R1S + k], ww, h0);
            h1 = fmaf(R1[1*R1S + k], ww, h1);
            h2 = fmaf(R1[2*R1S + k], ww, h2);
        }
        R2[0*R2S + tid] = h0; R2[1*R2S + tid] = h1; R2[2*R2S + tid] = h2;
    }

    // main GEMM (32x128)@(128x512) via tf32 mma: 16 warps = 2 m-rows x 8 n-groups(64)
    {
        int g = lane >> 2, tig = lane & 3;
        int m0 = (w >> 3) * 16, nbase = (w & 7) * 64;
        float d[8][4];
        #pragma unroll
        for (int nt = 0; nt < 8; nt++) { d[nt][0]=0.f; d[nt][1]=0.f; d[nt][2]=0.f; d[nt][3]=0.f; }
        #pragma unroll 4
        for (int kk = 0; kk < 16; kk++) {
            int k0 = kk * 8;
            const float* Ar = R1 + k0 + tig;
            uint32_t a0 = f2tf(Ar[(3 + m0 + g)*R1S]);
            uint32_t a1 = f2tf(Ar[(3 + m0 + g + 8)*R1S]);
            uint32_t a2 = f2tf(Ar[(3 + m0 + g)*R1S + 4]);
            uint32_t a3 = f2tf(Ar[(3 + m0 + g + 8)*R1S + 4]);
            const float* Bp = W_in + (size_t)(k0 + tig)*512 + g;
            #pragma unroll
            for (int nt = 0; nt < 8; nt++) {
                int n0 = nbase + nt*8;
                uint32_t b0 = f2tf(__ldg(&Bp[n0]));
                uint32_t b1 = f2tf(__ldg(&Bp[n0 + 4*512]));
                mma_tf32(d[nt][0], d[nt][1], d[nt][2], d[nt][3], a0, a1, a2, a3, b0, b1);
            }
        }
        int r0 = m0 + g, r1 = r0 + 8, c2 = 2*tig;
        #pragma unroll
        for (int nt = 0; nt < 8; nt++) {
            int cc = nbase + nt*8 + c2;
            if (cc < 256) {                                       // xb -> R2 rows 3..34
                *reinterpret_cast<float2*>(&R2[(3 + r0)*R2S + cc]) = make_float2(d[nt][0], d[nt][1]);
                *reinterpret_cast<float2*>(&R2[(3 + r1)*R2S + cc]) = make_float2(d[nt][2], d[nt][3]);
            } else {                                              // z -> global
                *reinterpret_cast<float2*>(&g_z[(size_t)(row0 + r0)*DI + cc - 256]) = make_float2(d[nt][0], d[nt][1]);
                *reinterpret_cast<float2*>(&g_z[(size_t)(row0 + r1)*DI + cc - 256]) = make_float2(d[nt][2], d[nt][3]);
            }
        }
    }
    __syncthreads();

    // conv4 + SiLU along tokens, reading xb from R2, writing xs into R2 rows 0..31
    if (tid < 256) {
        float4 cw = reinterpret_cast<const float4*>(conv_w)[tid];
        float cb = conv_b[tid];
        float x0 = R2[0*R2S + tid], x1 = R2[1*R2S + tid], x2 = R2[2*R2S + tid];
        #pragma unroll
        for (int t = 0; t < 32; t++) {
            float x3 = R2[(3 + t)*R2S + tid];
            float a = cb;
            a = fmaf(cw.x, x0, a); a = fmaf(cw.y, x1, a);
            a = fmaf(cw.z, x2, a); a = fmaf(cw.w, x3, a);
            R2[t*R2S + tid] = siluf(a);                           // safe: row t = token t-3's xb, dead
            x0 = x1; x1 = x2; x2 = x3;
        }
    }
    __syncthreads();

    // dbc GEMM (32x256)@(256x40) via tf32 mma: 10 warps = 2 m-tiles x 5 n-groups(8)
    if (w < 10) {
        int g = lane >> 2, tig = lane & 3;
        int m0 = (w / 5) * 16, n0 = (w % 5) * 8;
        float d0 = 0.f, d1 = 0.f, d2 = 0.f, d3 = 0.f;
        #pragma unroll 4
        for (int kk = 0; kk < 32; kk++) {
            int k0 = kk * 8;
            uint32_t a0 = f2tf(R2[(m0 + g)*R2S + k0 + tig]);
            uint32_t a1 = f2tf(R2[(m0 + g + 8)*R2S + k0 + tig]);
            uint32_t a2 = f2tf(R2[(m0 + g)*R2S + k0 + tig + 4]);
            uint32_t a3 = f2tf(R2[(m0 + g + 8)*R2S + k0 + tig + 4]);
            const float* Bp = W_xp + (size_t)(k0 + tig)*40 + g;
            uint32_t b0 = f2tf(__ldg(&Bp[n0]));
            uint32_t b1 = f2tf(__ldg(&Bp[n0 + 4*40]));
            mma_tf32(d0, d1, d2, d3, a0, a1, a2, a3, b0, b1);
        }
        int r0 = m0 + g, r1 = r0 + 8, cc = n0 + 2*tig;
        *reinterpret_cast<float2*>(&sdbc[r0*40 + cc]) = make_float2(d0, d1);
        *reinterpret_cast<float2*>(&sdbc[r1*40 + cc]) = make_float2(d2, d3);
    }
    __syncthreads();

    // delta = softplus(dbc[:, :8] @ W_dt + b_dt); write (delta, xs) float2
    if (tid < 256) {
        float wdt[8];
        #pragma unroll
        for (int r = 0; r < 8; r++) wdt[r] = W_dt[r*DI + tid];
        float bd = b_dt[tid];
        float2* __restrict__ dxp = reinterpret_cast<float2*>(g_dx) + (size_t)row0*DI + tid;
        #pragma unroll 2
        for (int t2 = 0; t2 < 32; t2++) {
            float a = bd;
            #pragma unroll
            for (int r = 0; r < 8; r++) a = fmaf(sdbc[t2*40 + r], wdt[r], a);
            float dl = (a > 20.f) ? a : log1pf(__expf(a));
            float xsv = R2[t2*R2S + tid];
            dxp[t2*DI] = make_float2(dl, xsv);
        }
    }
    // stash B,C as 8 quads per token: quad q = (B_q, C_q, B_{q+8}, C_{q+8})
    for (int i = tid; i < 1024; i += 512) {
        int t2 = i >> 5, v = i & 31;
        int dst;
        if (v < 16) { int s = v;      dst = (s < 8) ? 4*s     : 4*(s-8) + 2; }
        else        { int s = v - 16; dst = (s < 8) ? 4*s + 1 : 4*(s-8) + 3; }
        g_bc[(row0+t2)*32 + dst] = sdbc[t2*40 + 8 + v];
    }
}

// -------- K3: selective scan, 2 states/thread, smem-staged; writes GATED y --------
__global__ void __launch_bounds__(128) k_scan(const float* __restrict__ A_log,
                                              const float* __restrict__ D_ssm) {
    int dch = blockIdx.x, bm = blockIdx.y;           // grid (16, 32)
    int tid = threadIdx.x;                           // 128 = 16 ch x 8 q
    int q = tid & 7, ch = tid >> 3;
    int d = dch*16 + ch;
    __shared__ __align__(16) float2 s_dx[2][64*16];
    __shared__ __align__(16) float4 s_bc[2][64*8];
    float Aa0 = -__expf(A_log[d*16 + q]);
    float Aa1 = -__expf(A_log[d*16 + q + 8]);
    float Dd = D_ssm[d];
    float h0 = 0.f, h1 = 0.f;
    const float4* __restrict__ dx4 = reinterpret_cast<const float4*>(g_dx)
                                     + (size_t)bm*NP*128 + dch*8;
    const float4* __restrict__ bc4 = reinterpret_cast<const float4*>(g_bc)
                                     + (size_t)bm*NP*8;
    float4 rdx[4], rbc[4];
    #pragma unroll
    for (int j = 0; j < 4; j++) {
        int i = tid + j*128;
        int t = i >> 3, qq = i & 7;
        rdx[j] = __ldg(&dx4[(size_t)t*128 + qq]);
        rbc[j] = __ldg(&bc4[(size_t)t*8 + qq]);
    }
    {
        float4* sd = reinterpret_cast<float4*>(&s_dx[0][0]);
        float4* sb = reinterpret_cast<float4*>(&s_bc[0][0]);
        #pragma unroll
        for (int j = 0; j < 4; j++) { sd[tid + j*128] = rdx[j]; sb[tid + j*128] = rbc[j]; }
    }
    __syncthreads();
    int yb = bm*NP*DI + d;
    for (int c = 0; c < 4; c++) {
        int cur = c & 1;
        if (c < 3) {
            int bt = (c+1)*64;
            #pragma unroll
            for (int j = 0; j < 4; j++) {
                int i = tid + j*128;
                int t = i >> 3, qq = i & 7;
                rdx[j] = __ldg(&dx4[(size_t)(bt+t)*128 + qq]);
                rbc[j] = __ldg(&bc4[(size_t)(bt+t)*8 + qq]);
            }
        }
        const float2* __restrict__ dxrow = &s_dx[cur][ch];
        const float4* __restrict__ bcrow = &s_bc[cur][q];
        #pragma unroll 4
        for (int t = 0; t < 64; t += 4) {
            float2 dxa = dxrow[(t+0)*16], dxb = dxrow[(t+1)*16];
            float2 dxc = dxrow[(t+2)*16], dxd = dxrow[(t+3)*16];
            float4 bca = bcrow[(t+0)*8],  bcb = bcrow[(t+1)*8];
            float4 bcc = bcrow[(t+2)*8],  bcd = bcrow[(t+3)*8];
            float eA0 = __expf(dxa.x*Aa0), eA1 = __expf(dxa.x*Aa1);
            float eB0 = __expf(dxb.x*Aa0), eB1 = __expf(dxb.x*Aa1);
            float eC0 = __expf(dxc.x*Aa0), eC1 = __expf(dxc.x*Aa1);
            float eD0 = __expf(dxd.x*Aa0), eD1 = __expf(dxd.x*Aa1);
            float bxa = dxa.x*dxa.y, bxb = dxb.x*dxb.y;
            float bxc = dxc.x*dxc.y, bxd = dxd.x*dxd.y;
            h0 = fmaf(eA0, h0, bxa*bca.x); h1 = fmaf(eA1, h1, bxa*bca.z);
            float pa = fmaf(h1, bca.w, h0*bca.y);
            h0 = fmaf(eB0, h0, bxb*bcb.x); h1 = fmaf(eB1, h1, bxb*bcb.z);
            float pb = fmaf(h1, bcb.w, h0*bcb.y);
            h0 = fmaf(eC0, h0, bxc*bcc.x); h1 = fmaf(eC1, h1, bxc*bcc.z);
            float pc = fmaf(h1, bcc.w, h0*bcc.y);
            h0 = fmaf(eD0, h0, bxd*bcd.x); h1 = fmaf(eD1, h1, bxd*bcd.z);
            float pd = fmaf(h1, bcd.w, h0*bcd.y);
            #pragma unroll
            for (int o = 4; o > 0; o >>= 1) {
                pa += __shfl_xor_sync(0xffffffffu, pa, o);
                pb += __shfl_xor_sync(0xffffffffu, pb, o);
                pc += __shfl_xor_sync(0xffffffffu, pc, o);
                pd += __shfl_xor_sync(0xffffffffu, pd, o);
            }
            if (q == 0) {
                int tg = c*64 + t;
                float za = __ldg(&g_z[yb + (tg+0)*DI]);
                float zb = __ldg(&g_z[yb + (tg+1)*DI]);
                float zc = __ldg(&g_z[yb + (tg+2)*DI]);
                float zd = __ldg(&g_z[yb + (tg+3)*DI]);
                g_y[yb + (tg+0)*DI] = fmaf(Dd, dxa.y, pa) * siluf(za);
                g_y[yb + (tg+1)*DI] = fmaf(Dd, dxb.y, pb) * siluf(zb);
                g_y[yb + (tg+2)*DI] = fmaf(Dd, dxc.y, pc) * siluf(zc);
                g_y[yb + (tg+3)*DI] = fmaf(Dd, dxd.y, pd) * siluf(zd);
            }
        }
        if (c < 3) {
            float4* sd = reinterpret_cast<float4*>(&s_dx[cur^1][0]);
            float4* sb = reinterpret_cast<float4*>(&s_bc[cur^1][0]);
            #pragma unroll
            for (int j = 0; j < 4; j++) { sd[tid + j*128] = rdx[j]; sb[tid + j*128] = rbc[j]; }
            __syncthreads();
        }
    }
}

// -------- K4: tf32-MMA GEMM (32 x 256)@(256 x 128) on gated y, residual add --------
#define SHS 260   /* 260 mod 32 = 4 -> A-frag banks conflict-free */
__global__ void k_out(const float* __restrict__ W_out) {
    int row0 = blockIdx.x * 32, tid = threadIdx.x;   // 512 threads, 32 rows
    __shared__ __align__(16) float sh[32*SHS];
    {
        const float4* __restrict__ gy4 = reinterpret_cast<const float4*>(g_y) + (size_t)row0*64;
        for (int i4 = tid; i4 < 2048; i4 += 512) {
            int e = i4 * 4;
            *reinterpret_cast<float4*>(&sh[(e>>8)*SHS + (e&255)]) = __ldg(&gy4[i4]);
        }
    }
    __syncthreads();
    int w = tid >> 5, lane = tid & 31;
    int g = lane >> 2, tig = lane & 3;
    int m0 = (w >> 3) * 16, nbase = (w & 7) * 16;    // 2 m-tiles x 8 n-groups of 16
    float d[2][4];
    #pragma unroll
    for (int nt = 0; nt < 2; nt++) { d[nt][0]=0.f; d[nt][1]=0.f; d[nt][2]=0.f; d[nt][3]=0.f; }
    #pragma unroll 4
    for (int kk = 0; kk < 32; kk++) {
        int k0 = kk * 8;
        uint32_t a0 = f2tf(sh[(m0 + g)*SHS + k0 + tig]);
        uint32_t a1 = f2tf(sh[(m0 + g + 8)*SHS + k0 + tig]);
        uint32_t a2 = f2tf(sh[(m0 + g)*SHS + k0 + tig + 4]);
        uint32_t a3 = f2tf(sh[(m0 + g + 8)*SHS + k0 + tig + 4]);
        const float* Bp = W_out + (size_t)(k0 + tig)*DM + g;
        #pragma unroll
        for (int nt = 0; nt < 2; nt++) {
            int n0 = nbase + nt*8;
            uint32_t b0 = f2tf(__ldg(&Bp[n0]));
            uint32_t b1 = f2tf(__ldg(&Bp[n0 + 4*DM]));
            mma_tf32(d[nt][0], d[nt][1], d[nt][2], d[nt][3], a0, a1, a2, a3, b0, b1);
        }
    }
    int r0 = m0 + g, r1 = r0 + 8, c2 = 2*tig;
    #pragma unroll
    for (int nt = 0; nt < 2; nt++) {
        int cc = nbase + nt*8 + c2;
        float2* p0 = reinterpret_cast<float2*>(&g_u[(size_t)(row0 + r0)*DM + cc]);
        float2* p1 = reinterpret_cast<float2*>(&g_u[(size_t)(row0 + r1)*DM + cc]);
        float2 u0 = *p0, u1 = *p1;
        u0.x += d[nt][0]; u0.y += d[nt][1];
        u1.x += d[nt][2]; u1.y += d[nt][3];
        *p0 = u0; *p1 = u1;
    }
}

// -------- K5: fused final RMSNorm+LayerNorm + tf32-MMA head chunk, padded smem --------
#define SFS 132   /* 132 mod 32 = 4 -> conflict-free A-frag loads */
__global__ void k_head(const float* __restrict__ rmsf_w, const float* __restrict__ ln_g,
                       const float* __restrict__ ln_b, const float* __restrict__ W_head) {
    int c = blockIdx.x, tid = threadIdx.x;           // 256 chunks of K=128, 384 threads
    __shared__ __align__(16) float sf[32*SFS];
    int c0 = c * 128;
    for (int i = tid; i < 32*128; i += 384) {
        sf[(i>>7)*SFS + (i&127)] = g_u[(i>>7)*KH + c0 + (i&127)];
    }
    __syncthreads();
    int w = tid >> 5, lane = tid & 31;
    for (int bm = w; bm < 32; bm += 12) {
        float* p = &sf[bm*SFS];
        float v[4];
        float ss = 0.f;
        #pragma unroll
        for (int q = 0; q < 4; q++) { v[q] = p[lane + 32*q]; ss += v[q]*v[q]; }
        #pragma unroll
        for (int o = 16; o > 0; o >>= 1) ss += __shfl_xor_sync(0xffffffffu, ss, o);
        float rs = rsqrtf(ss * (1.f/128.f) + EPSF);
        float a = 0.f, b = 0.f;
        #pragma unroll
        for (int q = 0; q < 4; q++) {
            v[q] = v[q] * rs * rmsf_w[lane + 32*q];
            a += v[q]; b += v[q]*v[q];
        }
        #pragma unroll
        for (int o = 16; o > 0; o >>= 1) {
            a += __shfl_xor_sync(0xffffffffu, a, o);
            b += __shfl_xor_sync(0xffffffffu, b, o);
        }
        float mu  = a * (1.f/128.f);
        float var = b * (1.f/128.f) - mu*mu;
        float rstd = rsqrtf(var + EPSF);
        #pragma unroll
        for (int q = 0; q < 4; q++) {
            int col = lane + 32*q;
            p[col] = (v[q] - mu) * rstd * ln_g[col] + ln_b[col];
        }
    }
    __syncthreads();
    int g = lane >> 2, tig = lane & 3;
    int m0 = (w / 6) * 16, nbase = (w % 6) * 16;
    float d[2][4];
    #pragma unroll
    for (int nt = 0; nt < 2; nt++) { d[nt][0]=0.f; d[nt][1]=0.f; d[nt][2]=0.f; d[nt][3]=0.f; }
    #pragma unroll 4
    for (int kk = 0; kk < 16; kk++) {
        int k0 = kk * 8;
        uint32_t a0 = f2tf(sf[(m0 + g)*SFS + k0 + tig]);
        uint32_t a1 = f2tf(sf[(m0 + g + 8)*SFS + k0 + tig]);
        uint32_t a2 = f2tf(sf[(m0 + g)*SFS + k0 + tig + 4]);
        uint32_t a3 = f2tf(sf[(m0 + g + 8)*SFS + k0 + tig + 4]);
        const float* Bp = W_head + (size_t)(c0 + k0 + tig)*PLEN + g;
        #pragma unroll
        for (int nt = 0; nt < 2; nt++) {
            int n0 = nbase + nt*8;
            uint32_t b0 = f2tf(__ldg(&Bp[n0]));
            uint32_t b1 = f2tf(__ldg(&Bp[n0 + 4*PLEN]));
            mma_tf32(d[nt][0], d[nt][1], d[nt][2], d[nt][3], a0, a1, a2, a3, b0, b1);
        }
    }
    int r0 = m0 + g, r1 = r0 + 8, c2 = 2*tig;
    #pragma unroll
    for (int nt = 0; nt < 2; nt++) {
        int cc = nbase + nt*8 + c2;
        *reinterpret_cast<float2*>(&g_part[((size_t)c*32 + r0)*PLEN + cc]) = make_float2(d[nt][0], d[nt][1]);
        *reinterpret_cast<float2*>(&g_part[((size_t)c*32 + r1)*PLEN + cc]) = make_float2(d[nt][2], d[nt][3]);
    }
}

// -------- K6: reduce partials, de-normalize, write output --------
__global__ void k_reduce(const float* __restrict__ b_head, float* __restrict__ out) {
    int bm = blockIdx.x, j = threadIdx.x;            // 32 blocks x 96 threads
    float acc = b_head[j];
    #pragma unroll 4
    for (int c = 0; c < 256; c++) acc += g_part[(c*32 + bm)*PLEN + j];
    out[bm*PLEN + j] = acc * g_std[bm] + g_mean[bm];
}

extern "C" void kernel_launch(void* const* d_in, const int* in_sizes, int n_in,
                              void* d_out, int out_size) {
    const float* x      = (const float*)d_in[0];
    const float* W_pe   = (const float*)d_in[1];
    const float* b_pe   = (const float*)d_in[2];
    const float* pos    = (const float*)d_in[3];
    const float* rms_w  = (const float*)d_in[4];
    const float* W_in   = (const float*)d_in[5];
    const float* conv_w = (const float*)d_in[6];
    const float* conv_b = (const float*)d_in[7];
    const float* W_xp   = (const float*)d_in[8];
    const float* W_dt   = (const float*)d_in[9];
    const float* b_dt   = (const float*)d_in[10];
    const float* A_log  = (const float*)d_in[11];
    const float* D_ssm  = (const float*)d_in[12];
    const float* W_out  = (const float*)d_in[13];
    const float* rmsf_w = (const float*)d_in[14];
    const float* ln_g   = (const float*)d_in[15];
    const float* ln_b   = (const float*)d_in[16];
    const float* W_head = (const float*)d_in[17];
    const float* b_head = (const float*)d_in[18];

    cudaFuncSetAttribute(k_in2, cudaFuncAttributeMaxDynamicSharedMemorySize, DSMEM_BYTES);

    k_stats<<<BMSZ, 256>>>(x);
    k_embed<<<dim3(NP, BMSZ), DM>>>(x, W_pe, b_pe, pos);

    for (int l = 0; l < 2; l++) {
        k_in2 <<<BMSZ*NP/32, 512, DSMEM_BYTES>>>(rms_w + l*DM, W_in + l*DM*2*DI,
                                                 conv_w + l*DI*4, conv_b + l*DI,
                                                 W_xp + l*DI*40, W_dt + l*DTR*DI, b_dt + l*DI);
        k_scan<<<dim3(16, BMSZ), 128>>>(A_log + l*DI*DS, D_ssm + l*DI);
        k_out <<<BMSZ*NP/32, 512>>>(W_out + l*DI*DM);
    }

    k_head<<<KH/128, 384>>>(rmsf_w, ln_g, ln_b, W_head);
    k_reduce<<<BMSZ, PLEN>>>(b_head, (float*)d_out);
}

// round 17
// speedup vs baseline: 1.0725x; 1.0725x over previous
#include <cuda_runtime.h>
#include <math.h>
#include <stdint.h>

#define BMSZ 32
#define LSEQ 2048
#define NP   256
#define DM   128
#define DI   256
#define DS   16
#define DTR  8
#define PLEN 96
#define KH   (NP*DM)   /* 32768 */
#define EPSF 1e-5f

// k_in2 dynamic smem layout (floats): R1[35*132] | R2[35*260] | sdbc[32*40] | ssc[40]
#define R1S      132                  /* padded: A-frag banks (4g+tig) conflict-free */
#define R2S      260                  /* padded: dbc-MMA A-frag conflict-free */
#define R1_OFF   0
#define R2_OFF   (35*R1S)             /* 4620 */
#define SDBC_OFF (R2_OFF + 35*R2S)    /* 4620+9100 */
#define SSC_OFF  (SDBC_OFF+1280)
#define DSMEM_FLOATS (SSC_OFF+40)
#define DSMEM_BYTES  (DSMEM_FLOATS*4)

// -------- scratch (device globals; no allocation) --------
__device__ float g_mean[BMSZ];
__device__ float g_std[BMSZ];
__device__ float g_rstd[BMSZ];
__device__ __align__(16) float g_u[BMSZ*NP*DM];    // residual stream (4 MB)
__device__ __align__(16) float g_z[BMSZ*NP*DI];    // 8 MB
__device__ __align__(16) float g_dx[BMSZ*NP*DI*2]; // (delta, xs) interleaved, 16 MB
__device__ __align__(16) float g_bc[BMSZ*NP*32];   // per token, 8 quads (B_q,C_q,B_q+8,C_q+8)
__device__ __align__(16) float g_y[BMSZ*NP*DI];    // gated y (8 MB)
__device__ __align__(16) float g_part[256*BMSZ*PLEN];  // split-K head partials

__device__ __forceinline__ float siluf(float x) { return x / (1.f + __expf(-x)); }

__device__ __forceinline__ uint32_t f2tf(float x) {
    uint32_t u; asm("cvt.rna.tf32.f32 %0, %1;" : "=r"(u) : "f"(x)); return u;
}
__device__ __forceinline__ void mma_tf32(float& d0, float& d1, float& d2, float& d3,
                                         uint32_t a0, uint32_t a1, uint32_t a2, uint32_t a3,
                                         uint32_t b0, uint32_t b1) {
    asm volatile(
        "mma.sync.aligned.m16n8k8.row.col.f32.tf32.tf32.f32 "
        "{%0,%1,%2,%3},{%4,%5,%6,%7},{%8,%9},{%0,%1,%2,%3};"
        : "+f"(d0), "+f"(d1), "+f"(d2), "+f"(d3)
        : "r"(a0), "r"(a1), "r"(a2), "r"(a3), "r"(b0), "r"(b1));
}

// -------- K0: per-sequence mean/std over L --------
__global__ void k_stats(const float* __restrict__ x) {
    int bm = blockIdx.x, tid = threadIdx.x;
    float s = 0.f, s2 = 0.f;
    for (int i = tid; i < LSEQ; i += 256) {
        float v = x[bm*LSEQ + i];
        s += v; s2 += v*v;
    }
    __shared__ float sa[256], sb[256];
    sa[tid] = s; sb[tid] = s2; __syncthreads();
    for (int off = 128; off > 0; off >>= 1) {
        if (tid < off) { sa[tid] += sa[tid+off]; sb[tid] += sb[tid+off]; }
        __syncthreads();
    }
    if (tid == 0) {
        float m = sa[0] * (1.f/LSEQ);
        float var = sb[0] * (1.f/LSEQ) - m*m;
        float st = sqrtf(var + EPSF);
        g_mean[bm] = m; g_std[bm] = st; g_rstd[bm] = 1.f/st;
    }
}

// -------- K1: patch embedding: u = patches @ W_pe + b_pe + pos --------
__global__ void k_embed(const float* __restrict__ x, const float* __restrict__ W_pe,
                        const float* __restrict__ b_pe, const float* __restrict__ pos) {
    int p = blockIdx.x, bm = blockIdx.y, j = threadIdx.x;  // 128 threads
    __shared__ float sp[16];
    if (j < 16) {
        int t = p*8 + j; if (t > LSEQ-1) t = LSEQ-1;       // right-pad with last value
        sp[j] = (x[bm*LSEQ + t] - g_mean[bm]) * g_rstd[bm];
    }
    __syncthreads();
    float acc = b_pe[j] + pos[p*DM + j];
    #pragma unroll
    for (int k = 0; k < 16; k++) acc = fmaf(sp[k], W_pe[k*DM + j], acc);
    g_u[(bm*NP + p)*DM + j] = acc;
}

// -------- K2: RMSNorm + tf32 W_in GEMM + conv4/SiLU + tf32 dbc GEMM + delta + BC --------
__global__ void k_in2(const float* __restrict__ rms_w, const float* __restrict__ W_in,
                      const float* __restrict__ conv_w, const float* __restrict__ conv_b,
                      const float* __restrict__ W_xp, const float* __restrict__ W_dt,
                      const float* __restrict__ b_dt) {
    extern __shared__ __align__(16) float dsm[];
    float* R1   = dsm + R1_OFF;       // [35][R1S] normalized u (rows 0..2 halo)
    float* R2   = dsm + R2_OFF;       // [35][R2S] xb (then xs in rows 0..31)
    float* sdbc = dsm + SDBC_OFF;     // [32][40]
    float* ssc  = dsm + SSC_OFF;
    int row0 = blockIdx.x * 32, tid = threadIdx.x;

    bool seqstart = (row0 & (NP-1)) == 0;
    for (int i = tid; i < 32*128; i += 512) R1[(3 + (i>>7))*R1S + (i&127)] = g_u[row0*DM + i];
    if (seqstart) { for (int i = tid; i < 3*128; i += 512) R1[(i>>7)*R1S + (i&127)] = 0.f; }
    else          { for (int i = tid; i < 3*128; i += 512) R1[(i>>7)*R1S + (i&127)] = g_u[(row0-3)*DM + i]; }
    __syncthreads();

    int w = tid >> 5, lane = tid & 31;
    for (int r = w; r < 35; r += 16) {
        float ss = 0.f;
        #pragma unroll
        for (int q = 0; q < 4; q++) { float v = R1[r*R1S + lane + 32*q]; ss += v*v; }
        #pragma unroll
        for (int o = 16; o > 0; o >>= 1) ss += __shfl_xor_sync(0xffffffffu, ss, o);
        if (lane == 0) ssc[r] = rsqrtf(ss * (1.f/128.f) + EPSF);
    }
    __syncthreads();
    for (int i = tid; i < 35*128; i += 512) {
        int r = i>>7, k = i&127;
        R1[r*R1S + k] *= ssc[r] * rms_w[k];
    }
    __syncthreads();

    // halo xb rows (tokens -3..-1) scalar -> R2 rows 0..2
    if (tid < 256) {
        float h0 = 0.f, h1 = 0.f, h2 = 0.f;
        for (int k = 0; k < 128; k++) {
            float ww = __ldg(&W_in[k*512 + tid]);
            h0 = fmaf(R1[0*R1S + k], ww, h0);
            h1 = fmaf(R1[1*R1S + k], ww, h1);
            h2 = fmaf(R1[2*R1S + k], ww, h2);
        }
        R2[0*R2S + tid] = h0; R2[1*R2S + tid] = h1; R2[2*R2S + tid] = h2;
    }

    // main GEMM (32x128)@(128x512) via tf32 mma: 16 warps = 2 m-rows x 8 n-groups(64)
    {
        int g = lane >> 2, tig = lane & 3;
        int m0 = (w >> 3) * 16, nbase = (w & 7) * 64;
        float d[8][4];
        #pragma unroll
        for (int nt = 0; nt < 8; nt++) { d[nt][0]=0.f; d[nt][1]=0.f; d[nt][2]=0.f; d[nt][3]=0.f; }
        #pragma unroll 4
        for (int kk = 0; kk < 16; kk++) {
            int k0 = kk * 8;
            const float* Ar = R1 + k0 + tig;
            uint32_t a0 = f2tf(Ar[(3 + m0 + g)*R1S]);
            uint32_t a1 = f2tf(Ar[(3 + m0 + g + 8)*R1S]);
            uint32_t a2 = f2tf(Ar[(3 + m0 + g)*R1S + 4]);
            uint32_t a3 = f2tf(Ar[(3 + m0 + g + 8)*R1S + 4]);
            const float* Bp = W_in + (size_t)(k0 + tig)*512 + g;
            #pragma unroll
            for (int nt = 0; nt < 8; nt++) {
                int n0 = nbase + nt*8;
                uint32_t b0 = f2tf(__ldg(&Bp[n0]));
                uint32_t b1 = f2tf(__ldg(&Bp[n0 + 4*512]));
                mma_tf32(d[nt][0], d[nt][1], d[nt][2], d[nt][3], a0, a1, a2, a3, b0, b1);
            }
        }
        int r0 = m0 + g, r1 = r0 + 8, c2 = 2*tig;
        #pragma unroll
        for (int nt = 0; nt < 8; nt++) {
            int cc = nbase + nt*8 + c2;
            if (cc < 256) {                                       // xb -> R2 rows 3..34
                *reinterpret_cast<float2*>(&R2[(3 + r0)*R2S + cc]) = make_float2(d[nt][0], d[nt][1]);
                *reinterpret_cast<float2*>(&R2[(3 + r1)*R2S + cc]) = make_float2(d[nt][2], d[nt][3]);
            } else {                                              // z -> global
                *reinterpret_cast<float2*>(&g_z[(size_t)(row0 + r0)*DI + cc - 256]) = make_float2(d[nt][0], d[nt][1]);
                *reinterpret_cast<float2*>(&g_z[(size_t)(row0 + r1)*DI + cc - 256]) = make_float2(d[nt][2], d[nt][3]);
            }
        }
    }
    __syncthreads();

    // conv4 + SiLU along tokens, reading xb from R2, writing xs into R2 rows 0..31
    if (tid < 256) {
        float4 cw = reinterpret_cast<const float4*>(conv_w)[tid];
        float cb = conv_b[tid];
        float x0 = R2[0*R2S + tid], x1 = R2[1*R2S + tid], x2 = R2[2*R2S + tid];
        #pragma unroll
        for (int t = 0; t < 32; t++) {
            float x3 = R2[(3 + t)*R2S + tid];
            float a = cb;
            a = fmaf(cw.x, x0, a); a = fmaf(cw.y, x1, a);
            a = fmaf(cw.z, x2, a); a = fmaf(cw.w, x3, a);
            R2[t*R2S + tid] = siluf(a);                           // safe: row t = token t-3's xb, dead
            x0 = x1; x1 = x2; x2 = x3;
        }
    }
    __syncthreads();

    // dbc GEMM (32x256)@(256x40) via tf32 mma: 10 warps = 2 m-tiles x 5 n-groups(8)
    if (w < 10) {
        int g = lane >> 2, tig = lane & 3;
        int m0 = (w / 5) * 16, n0 = (w % 5) * 8;
        float d0 = 0.f, d1 = 0.f, d2 = 0.f, d3 = 0.f;
        #pragma unroll 4
        for (int kk = 0; kk < 32; kk++) {
            int k0 = kk * 8;
            uint32_t a0 = f2tf(R2[(m0 + g)*R2S + k0 + tig]);
            uint32_t a1 = f2tf(R2[(m0 + g + 8)*R2S + k0 + tig]);
            uint32_t a2 = f2tf(R2[(m0 + g)*R2S + k0 + tig + 4]);
            uint32_t a3 = f2tf(R2[(m0 + g + 8)*R2S + k0 + tig + 4]);
            const float* Bp = W_xp + (size_t)(k0 + tig)*40 + g;
            uint32_t b0 = f2tf(__ldg(&Bp[n0]));
            uint32_t b1 = f2tf(__ldg(&Bp[n0 + 4*40]));
            mma_tf32(d0, d1, d2, d3, a0, a1, a2, a3, b0, b1);
        }
        int r0 = m0 + g, r1 = r0 + 8, cc = n0 + 2*tig;
        *reinterpret_cast<float2*>(&sdbc[r0*40 + cc]) = make_float2(d0, d1);
        *reinterpret_cast<float2*>(&sdbc[r1*40 + cc]) = make_float2(d2, d3);
    }
    __syncthreads();

    // delta = softplus(dbc[:, :8] @ W_dt + b_dt); write (delta, xs) float2
    if (tid < 256) {
        float wdt[8];
        #pragma unroll
        for (int r = 0; r < 8; r++) wdt[r] = W_dt[r*DI + tid];
        float bd = b_dt[tid];
        float2* __restrict__ dxp = reinterpret_cast<float2*>(g_dx) + (size_t)row0*DI + tid;
        #pragma unroll 2
        for (int t2 = 0; t2 < 32; t2++) {
            float a = bd;
            #pragma unroll
            for (int r = 0; r < 8; r++) a = fmaf(sdbc[t2*40 + r], wdt[r], a);
            float dl = (a > 20.f) ? a : log1pf(__expf(a));
            float xsv = R2[t2*R2S + tid];
            dxp[t2*DI] = make_float2(dl, xsv);
        }
    }
    // stash B,C as 8 quads per token: quad q = (B_q, C_q, B_{q+8}, C_{q+8})
    for (int i = tid; i < 1024; i += 512) {
        int t2 = i >> 5, v = i & 31;
        int dst;
        if (v < 16) { int s = v;      dst = (s < 8) ? 4*s     : 4*(s-8) + 2; }
        else        { int s = v - 16; dst = (s < 8) ? 4*s + 1 : 4*(s-8) + 3; }
        g_bc[(row0+t2)*32 + dst] = sdbc[t2*40 + 8 + v];
    }
}

// -------- K3: selective scan; z staged through smem; writes GATED y --------
__global__ void __launch_bounds__(128) k_scan(const float* __restrict__ A_log,
                                              const float* __restrict__ D_ssm) {
    int dch = blockIdx.x, bm = blockIdx.y;           // grid (16, 32)
    int tid = threadIdx.x;                           // 128 = 16 ch x 8 q
    int q = tid & 7, ch = tid >> 3;
    int d = dch*16 + ch;
    __shared__ __align__(16) float2 s_dx[2][64*16];  // 8KB each
    __shared__ __align__(16) float4 s_bc[2][64*8];   // 8KB each
    __shared__ __align__(16) float  s_z [2][64*16];  // 4KB each
    float Aa0 = -__expf(A_log[d*16 + q]);
    float Aa1 = -__expf(A_log[d*16 + q + 8]);
    float Dd = D_ssm[d];
    float h0 = 0.f, h1 = 0.f;
    const float4* __restrict__ dx4 = reinterpret_cast<const float4*>(g_dx)
                                     + (size_t)bm*NP*128 + dch*8;        // token stride 128
    const float4* __restrict__ bc4 = reinterpret_cast<const float4*>(g_bc)
                                     + (size_t)bm*NP*8;                   // token stride 8
    const float4* __restrict__ z4  = reinterpret_cast<const float4*>(g_z)
                                     + (size_t)bm*NP*64 + dch*4;          // token stride 64
    float4 rdx[4], rbc[4], rz[2];
    #pragma unroll
    for (int j = 0; j < 4; j++) {                    // chunk 0: dx/bc
        int i = tid + j*128;
        int t = i >> 3, qq = i & 7;
        rdx[j] = __ldg(&dx4[(size_t)t*128 + qq]);
        rbc[j] = __ldg(&bc4[(size_t)t*8 + qq]);
    }
    #pragma unroll
    for (int j = 0; j < 2; j++) {                    // chunk 0: z (64 tok x 4 quads)
        int i = tid + j*128;
        int t = i >> 2, qz = i & 3;
        rz[j] = __ldg(&z4[(size_t)t*64 + qz]);
    }
    {
        float4* sd = reinterpret_cast<float4*>(&s_dx[0][0]);
        float4* sb = reinterpret_cast<float4*>(&s_bc[0][0]);
        float4* sz = reinterpret_cast<float4*>(&s_z[0][0]);
        #pragma unroll
        for (int j = 0; j < 4; j++) { sd[tid + j*128] = rdx[j]; sb[tid + j*128] = rbc[j]; }
        #pragma unroll
        for (int j = 0; j < 2; j++) sz[tid + j*128] = rz[j];
    }
    __syncthreads();
    int yb = bm*NP*DI + d;
    for (int c = 0; c < 4; c++) {
        int cur = c & 1;
        if (c < 3) {                                 // prefetch chunk c+1 into regs
            int bt = (c+1)*64;
            #pragma unroll
            for (int j = 0; j < 4; j++) {
                int i = tid + j*128;
                int t = i >> 3, qq = i & 7;
                rdx[j] = __ldg(&dx4[(size_t)(bt+t)*128 + qq]);
                rbc[j] = __ldg(&bc4[(size_t)(bt+t)*8 + qq]);
            }
            #pragma unroll
            for (int j = 0; j < 2; j++) {
                int i = tid + j*128;
                int t = i >> 2, qz = i & 3;
                rz[j] = __ldg(&z4[(size_t)(bt+t)*64 + qz]);
            }
        }
        const float2* __restrict__ dxrow = &s_dx[cur][ch];
        const float4* __restrict__ bcrow = &s_bc[cur][q];
        const float*  __restrict__ zrow  = &s_z[cur][ch];
        #pragma unroll 4
        for (int t = 0; t < 64; t += 4) {
            float2 dxa = dxrow[(t+0)*16], dxb = dxrow[(t+1)*16];
            float2 dxc = dxrow[(t+2)*16], dxd = dxrow[(t+3)*16];
            float4 bca = bcrow[(t+0)*8],  bcb = bcrow[(t+1)*8];
            float4 bcc = bcrow[(t+2)*8],  bcd = bcrow[(t+3)*8];
            float eA0 = __expf(dxa.x*Aa0), eA1 = __expf(dxa.x*Aa1);
            float eB0 = __expf(dxb.x*Aa0), eB1 = __expf(dxb.x*Aa1);
            float eC0 = __expf(dxc.x*Aa0), eC1 = __expf(dxc.x*Aa1);
            float eD0 = __expf(dxd.x*Aa0), eD1 = __expf(dxd.x*Aa1);
            float bxa = dxa.x*dxa.y, bxb = dxb.x*dxb.y;
            float bxc = dxc.x*dxc.y, bxd = dxd.x*dxd.y;
            h0 = fmaf(eA0, h0, bxa*bca.x); h1 = fmaf(eA1, h1, bxa*bca.z);
            float pa = fmaf(h1, bca.w, h0*bca.y);
            h0 = fmaf(eB0, h0, bxb*bcb.x); h1 = fmaf(eB1, h1, bxb*bcb.z);
            float pb = fmaf(h1, bcb.w, h0*bcb.y);
            h0 = fmaf(eC0, h0, bxc*bcc.x); h1 = fmaf(eC1, h1, bxc*bcc.z);
            float pc = fmaf(h1, bcc.w, h0*bcc.y);
            h0 = fmaf(eD0, h0, bxd*bcd.x); h1 = fmaf(eD1, h1, bxd*bcd.z);
            float pd = fmaf(h1, bcd.w, h0*bcd.y);
            #pragma unroll
            for (int o = 4; o > 0; o >>= 1) {
                pa += __shfl_xor_sync(0xffffffffu, pa, o);
                pb += __shfl_xor_sync(0xffffffffu, pb, o);
                pc += __shfl_xor_sync(0xffffffffu, pc, o);
                pd += __shfl_xor_sync(0xffffffffu, pd, o);
            }
            if (q == 0) {
                int tg = c*64 + t;
                float za = zrow[(t+0)*16], zb = zrow[(t+1)*16];
                float zc = zrow[(t+2)*16], zd = zrow[(t+3)*16];
                g_y[yb + (tg+0)*DI] = fmaf(Dd, dxa.y, pa) * siluf(za);
                g_y[yb + (tg+1)*DI] = fmaf(Dd, dxb.y, pb) * siluf(zb);
                g_y[yb + (tg+2)*DI] = fmaf(Dd, dxc.y, pc) * siluf(zc);
                g_y[yb + (tg+3)*DI] = fmaf(Dd, dxd.y, pd) * siluf(zd);
            }
        }
        if (c < 3) {                                 // commit prefetched chunk, flip buffers
            float4* sd = reinterpret_cast<float4*>(&s_dx[cur^1][0]);
            float4* sb = reinterpret_cast<float4*>(&s_bc[cur^1][0]);
            float4* sz = reinterpret_cast<float4*>(&s_z[cur^1][0]);
            #pragma unroll
            for (int j = 0; j < 4; j++) { sd[tid + j*128] = rdx[j]; sb[tid + j*128] = rbc[j]; }
            #pragma unroll
            for (int j = 0; j < 2; j++) sz[tid + j*128] = rz[j];
            __syncthreads();
        }
    }
}

// -------- K4: tf32-MMA GEMM (32 x 256)@(256 x 128) on gated y, residual add --------
#define SHS 260   /* 260 mod 32 = 4 -> A-frag banks conflict-free */
__global__ void k_out(const float* __restrict__ W_out) {
    int row0 = blockIdx.x * 32, tid = threadIdx.x;   // 512 threads, 32 rows
    __shared__ __align__(16) float sh[32*SHS];
    {
        const float4* __restrict__ gy4 = reinterpret_cast<const float4*>(g_y) + (size_t)row0*64;
        for (int i4 = tid; i4 < 2048; i4 += 512) {
            int e = i4 * 4;
            *reinterpret_cast<float4*>(&sh[(e>>8)*SHS + (e&255)]) = __ldg(&gy4[i4]);
        }
    }
    __syncthreads();
    int w = tid >> 5, lane = tid & 31;
    int g = lane >> 2, tig = lane & 3;
    int m0 = (w >> 3) * 16, nbase = (w & 7) * 16;    // 2 m-tiles x 8 n-groups of 16
    float d[2][4];
    #pragma unroll
    for (int nt = 0; nt < 2; nt++) { d[nt][0]=0.f; d[nt][1]=0.f; d[nt][2]=0.f; d[nt][3]=0.f; }
    #pragma unroll 4
    for (int kk = 0; kk < 32; kk++) {
        int k0 = kk * 8;
        uint32_t a0 = f2tf(sh[(m0 + g)*SHS + k0 + tig]);
        uint32_t a1 = f2tf(sh[(m0 + g + 8)*SHS + k0 + tig]);
        uint32_t a2 = f2tf(sh[(m0 + g)*SHS + k0 + tig + 4]);
        uint32_t a3 = f2tf(sh[(m0 + g + 8)*SHS + k0 + tig + 4]);
        const float* Bp = W_out + (size_t)(k0 + tig)*DM + g;
        #pragma unroll
        for (int nt = 0; nt < 2; nt++) {
            int n0 = nbase + nt*8;
            uint32_t b0 = f2tf(__ldg(&Bp[n0]));
            uint32_t b1 = f2tf(__ldg(&Bp[n0 + 4*DM]));
            mma_tf32(d[nt][0], d[nt][1], d[nt][2], d[nt][3], a0, a1, a2, a3, b0, b1);
        }
    }
    int r0 = m0 + g, r1 = r0 + 8, c2 = 2*tig;
    #pragma unroll
    for (int nt = 0; nt < 2; nt++) {
        int cc = nbase + nt*8 + c2;
        float2* p0 = reinterpret_cast<float2*>(&g_u[(size_t)(row0 + r0)*DM + cc]);
        float2* p1 = reinterpret_cast<float2*>(&g_u[(size_t)(row0 + r1)*DM + cc]);
        float2 u0 = *p0, u1 = *p1;
        u0.x += d[nt][0]; u0.y += d[nt][1];
        u1.x += d[nt][2]; u1.y += d[nt][3];
        *p0 = u0; *p1 = u1;
    }
}

// -------- K5: fused final RMSNorm+LayerNorm + tf32-MMA head chunk, padded smem --------
#define SFS 132   /* 132 mod 32 = 4 -> conflict-free A-frag loads */
__global__ void k_head(const float* __restrict__ rmsf_w, const float* __restrict__ ln_g,
                       const float* __restrict__ ln_b, const float* __restrict__ W_head) {
    int c = blockIdx.x, tid = threadIdx.x;           // 256 chunks of K=128, 384 threads
    __shared__ __align__(16) float sf[32*SFS];
    int c0 = c * 128;
    for (int i = tid; i < 32*128; i += 384) {
        sf[(i>>7)*SFS + (i&127)] = g_u[(i>>7)*KH + c0 + (i&127)];
    }
    __syncthreads();
    int w = tid >> 5, lane = tid & 31;
    for (int bm = w; bm < 32; bm += 12) {
        float* p = &sf[bm*SFS];
        float v[4];
        float ss = 0.f;
        #pragma unroll
        for (int q = 0; q < 4; q++) { v[q] = p[lane + 32*q]; ss += v[q]*v[q]; }
        #pragma unroll
        for (int o = 16; o > 0; o >>= 1) ss += __shfl_xor_sync(0xffffffffu, ss, o);
        float rs = rsqrtf(ss * (1.f/128.f) + EPSF);
        float a = 0.f, b = 0.f;
        #pragma unroll
        for (int q = 0; q < 4; q++) {
            v[q] = v[q] * rs * rmsf_w[lane + 32*q];
            a += v[q]; b += v[q]*v[q];
        }
        #pragma unroll
        for (int o = 16; o > 0; o >>= 1) {
            a += __shfl_xor_sync(0xffffffffu, a, o);
            b += __shfl_xor_sync(0xffffffffu, b, o);
        }
        float mu  = a * (1.f/128.f);
        float var = b * (1.f/128.f) - mu*mu;
        float rstd = rsqrtf(var + EPSF);
        #pragma unroll
        for (int q = 0; q < 4; q++) {
            int col = lane + 32*q;
            p[col] = (v[q] - mu) * rstd * ln_g[col] + ln_b[col];
        }
    }
    __syncthreads();
    int g = lane >> 2, tig = lane & 3;
    int m0 = (w / 6) * 16, nbase = (w % 6) * 16;
    float d[2][4];
    #pragma unroll
    for (int nt = 0; nt < 2; nt++) { d[nt][0]=0.f; d[nt][1]=0.f; d[nt][2]=0.f; d[nt][3]=0.f; }
    #pragma unroll 4
    for (int kk = 0; kk < 16; kk++) {
        int k0 = kk * 8;
        uint32_t a0 = f2tf(sf[(m0 + g)*SFS + k0 + tig]);
        uint32_t a1 = f2tf(sf[(m0 + g + 8)*SFS + k0 + tig]);
        uint32_t a2 = f2tf(sf[(m0 + g)*SFS + k0 + tig + 4]);
        uint32_t a3 = f2tf(sf[(m0 + g + 8)*SFS + k0 + tig + 4]);
        const float* Bp = W_head + (size_t)(c0 + k0 + tig)*PLEN + g;
        #pragma unroll
        for (int nt = 0; nt < 2; nt++) {
            int n0 = nbase + nt*8;
            uint32_t b0 = f2tf(__ldg(&Bp[n0]));
            uint32_t b1 = f2tf(__ldg(&Bp[n0 + 4*PLEN]));
            mma_tf32(d[nt][0], d[nt][1], d[nt][2], d[nt][3], a0, a1, a2, a3, b0, b1);
        }
    }
    int r0 = m0 + g, r1 = r0 + 8, c2 = 2*tig;
    #pragma unroll
    for (int nt = 0; nt < 2; nt++) {
        int cc = nbase + nt*8 + c2;
        *reinterpret_cast<float2*>(&g_part[((size_t)c*32 + r0)*PLEN + cc]) = make_float2(d[nt][0], d[nt][1]);
        *reinterpret_cast<float2*>(&g_part[((size_t)c*32 + r1)*PLEN + cc]) = make_float2(d[nt][2], d[nt][3]);
    }
}

// -------- K6: reduce partials, de-normalize, write output --------
__global__ void k_reduce(const float* __restrict__ b_head, float* __restrict__ out) {
    int bm = blockIdx.x, j = threadIdx.x;            // 32 blocks x 96 threads
    float acc = b_head[j];
    #pragma unroll 4
    for (int c = 0; c < 256; c++) acc += g_part[(c*32 + bm)*PLEN + j];
    out[bm*PLEN + j] = acc * g_std[bm] + g_mean[bm];
}

extern "C" void kernel_launch(void* const* d_in, const int* in_sizes, int n_in,
                              void* d_out, int out_size) {
    const float* x      = (const float*)d_in[0];
    const float* W_pe   = (const float*)d_in[1];
    const float* b_pe   = (const float*)d_in[2];
    const float* pos    = (const float*)d_in[3];
    const float* rms_w  = (const float*)d_in[4];
    const float* W_in   = (const float*)d_in[5];
    const float* conv_w = (const float*)d_in[6];
    const float* conv_b = (const float*)d_in[7];
    const float* W_xp   = (const float*)d_in[8];
    const float* W_dt   = (const float*)d_in[9];
    const float* b_dt   = (const float*)d_in[10];
    const float* A_log  = (const float*)d_in[11];
    const float* D_ssm  = (const float*)d_in[12];
    const float* W_out  = (const float*)d_in[13];
    const float* rmsf_w = (const float*)d_in[14];
    const float* ln_g   = (const float*)d_in[15];
    const float* ln_b   = (const float*)d_in[16];
    const float* W_head = (const float*)d_in[17];
    const float* b_head = (const float*)d_in[18];

    cudaFuncSetAttribute(k_in2, cudaFuncAttributeMaxDynamicSharedMemorySize, DSMEM_BYTES);

    k_stats<<<BMSZ, 256>>>(x);
    k_embed<<<dim3(NP, BMSZ), DM>>>(x, W_pe, b_pe, pos);

    for (int l = 0; l < 2; l++) {
        k_in2 <<<BMSZ*NP/32, 512, DSMEM_BYTES>>>(rms_w + l*DM, W_in + l*DM*2*DI,
                                                 conv_w + l*DI*4, conv_b + l*DI,
                                                 W_xp + l*DI*40, W_dt + l*DTR*DI, b_dt + l*DI);
        k_scan<<<dim3(16, BMSZ), 128>>>(A_log + l*DI*DS, D_ssm + l*DI);
        k_out <<<BMSZ*NP/32, 512>>>(W_out + l*DI*DM);
    }

    k_head<<<KH/128, 384>>>(rmsf_w, ln_g, ln_b, W_head);
    k_reduce<<<BMSZ, PLEN>>>(b_head, (float*)d_out);
}